// round 14
// baseline (speedup 1.0000x reference)
#include <cuda_runtime.h>
#include <cstdint>

// ---------------------------------------------------------------------------
// MultiMolNet: per-atom typed 3-layer MLP + masked per-molecule sum.
// Identity: sum over all 8 type-MLPs = f_{type}(feats) + (C - Z_type),
// Z_t = f_t(0), C = sum_t Z_t  ->  one MLP eval per atom.
//
// R13: warp-autonomous layer-1 pipeline. R12 ncu: nothing saturated
//      (L1 59%, tensor 36%, issue 30%) -> serialization-bound by 8
//      block barriers. Each warp now stages ITS OWN 32 A-rows into a
//      warp-private double buffer (cp.async, per-thread wait_group),
//      so the mainloop has zero block barriers. BM=256, 2 m-tiles/warp,
//      B fragments precomputed per type in gmem (LDG.128 stream).
// ---------------------------------------------------------------------------

namespace {
constexpr int B_  = 4096;
constexpr int A_  = 64;
constexpr int F_  = 124;
constexpr int T_  = 8;
constexpr int H1_ = 64;
constexpr int H2_ = 16;
constexpr int NATOM = B_ * A_;     // 262144
constexpr int ROW   = F_ + 1;      // 125
constexpr int BM    = 256;         // atoms per CTA (two 128-row MMA tiles)
constexpr int MLP_BLOCKS = NATOM / BM + T_;   // 1032
constexpr int NKS   = 16;          // k-steps of 8 (124 padded to 128)

// --- smem layout (float indices) ---
// Warp-private A staging: [8 warps][2 bufs][32 rows][36 floats]
//   row stride 36 -> fragment reads hit banks 4r+c (conflict-free).
constexpr int AROW   = 36;
constexpr int ABUF_F = 32 * AROW;            // 1152 floats per buffer
constexpr int AW_F   = 2 * ABUF_F;           // 2304 per warp
constexpr int A_REG  = 8 * AW_F;             // 18432 total
// h1s[256][68] overlays [0..17408) after layer-1 (barrier-protected).
constexpr int U_H1S = 0;
constexpr int S_W2   = A_REG;                // 18432 (byte 73728, 16B aligned)
constexpr int S_B1   = S_W2 + 1024;
constexpr int S_B2   = S_B1 + 64;
constexpr int S_W3   = S_B2 + 16;
constexpr int S_MISC = S_W3 + 16;   // [0]=corr, [1]=b3
constexpr int S_IDX  = S_MISC + 4;  // 256 ints
constexpr int SMEM_FLOATS = S_IDX + BM;
constexpr int SMEM_BYTES  = SMEM_FLOATS * 4;   // 79248 B -> 2 CTAs/SM
}

// ---- scratch ----
__device__ int    g_counts[T_];
__device__ int    g_bucket[T_ * NATOM];
__device__ float  g_corr[T_];
__device__ float  g_atom[NATOM];
// B fragments per type: [16ks][8nt][32lane] x (h0,h1,l0,l1)
__device__ float4 g_bfrag[T_ * NKS * 8 * 32];   // 512 KB

// ---- helpers ----
__device__ __forceinline__ uint32_t smem_u32(const void* p) {
    return (uint32_t)__cvta_generic_to_shared(p);
}
__device__ __forceinline__ float tf32_hi(float x) {
    uint32_t u;
    asm("cvt.rna.tf32.f32 %0, %1;" : "=r"(u) : "f"(x));
    return __uint_as_float(u);
}
__device__ __forceinline__ void cp_async4(uint32_t dst, const void* src) {
    asm volatile("cp.async.ca.shared.global [%0], [%1], 4;"
                 :: "r"(dst), "l"(src) : "memory");
}
__device__ __forceinline__ void sts_zero(uint32_t dst) {
    asm volatile("st.shared.b32 [%0], %1;" :: "r"(dst), "r"(0u));
}
#define CP_COMMIT() asm volatile("cp.async.commit_group;" ::: "memory")
#define CP_WAIT(n)  asm volatile("cp.async.wait_group %0;" :: "n"(n) : "memory")

// m16n8k8 tf32 MMA: D(f32) += A(tf32) * B(tf32). Row-major A, col-major B.
__device__ __forceinline__ void mma_tf32(float d[4], const uint32_t a[4],
                                         uint32_t b0, uint32_t b1) {
    asm volatile(
        "mma.sync.aligned.m16n8k8.row.col.f32.tf32.tf32.f32 "
        "{%0,%1,%2,%3}, {%4,%5,%6,%7}, {%8,%9}, {%0,%1,%2,%3};"
        : "+f"(d[0]), "+f"(d[1]), "+f"(d[2]), "+f"(d[3])
        : "r"(a[0]), "r"(a[1]), "r"(a[2]), "r"(a[3]), "r"(b0), "r"(b1));
}

// ---- f32x2 packed FMA (layer 2) ----
__device__ __forceinline__ void ffma2(unsigned long long& d,
                                      unsigned long long a, unsigned long long b) {
    asm("fma.rn.f32x2 %0, %1, %2, %3;" : "=l"(d) : "l"(a), "l"(b), "l"(d));
}
__device__ __forceinline__ unsigned long long pack2(float lo, float hi) {
    unsigned long long r;
    asm("mov.b64 %0, {%1, %2};" : "=l"(r) : "f"(lo), "f"(hi));
    return r;
}
__device__ __forceinline__ void unpack2(unsigned long long v, float& lo, float& hi) {
    asm("mov.b64 {%0, %1}, %2;" : "=f"(lo), "=f"(hi) : "l"(v));
}

// ===========================================================================
// K0: Z_t = f_t(0), corr_t = C - Z_t; zero counters.
// ===========================================================================
__global__ void k_init(const float* __restrict__ b1, const float* __restrict__ W2,
                       const float* __restrict__ b2, const float* __restrict__ W3,
                       const float* __restrict__ b3) {
    __shared__ float zs[T_];
    int t = threadIdx.x;
    if (t < T_) {
        g_counts[t] = 0;
        float h1z[H1_];
        #pragma unroll
        for (int h = 0; h < H1_; h++) h1z[h] = fmaxf(b1[t * H1_ + h], 0.0f);
        float o = b3[t];
        for (int g = 0; g < H2_; g++) {
            float s = b2[t * H2_ + g];
            #pragma unroll
            for (int k = 0; k < H1_; k++)
                s += h1z[k] * W2[t * H1_ * H2_ + k * H2_ + g];
            o += fmaxf(s, 0.0f) * W3[t * H2_ + g];
        }
        zs[t] = o;
    }
    __syncthreads();
    if (t < T_) {
        float C = 0.0f;
        #pragma unroll
        for (int tt = 0; tt < T_; tt++) C += zs[tt];
        g_corr[t] = C - zs[t];
    }
}

// ===========================================================================
// K0b: precompute B (W1) hi/lo fragments per type. 64 blocks x 512.
// frag map (m16n8k8 B, col-major): b0=(k=l&3, n=l>>2), b1=(k+4, n)
// ===========================================================================
__global__ void k_binit(const float* __restrict__ W1) {
    int t    = blockIdx.x >> 3;
    int part = blockIdx.x & 7;
    const float* w = W1 + t * F_ * H1_;
    int s = part * 512 + threadIdx.x;
    {
        int l = s & 31, nt = (s >> 5) & 7, ks = s >> 8;
        int n  = nt * 8 + (l >> 2);
        int k0 = ks * 8 + (l & 3);
        float v0 = (k0 < F_)     ? w[k0 * H1_ + n]       : 0.0f;
        float v1 = (k0 + 4 < F_) ? w[(k0 + 4) * H1_ + n] : 0.0f;
        float h0 = tf32_hi(v0), h1 = tf32_hi(v1);
        g_bfrag[t * (NKS * 8 * 32) + s] = make_float4(h0, h1, v0 - h0, v1 - h1);
    }
}

// ===========================================================================
// K1: bucket atom indices by type (order nondeterminism harmless).
// ===========================================================================
__global__ void k_bucket(const float* __restrict__ x) {
    __shared__ int scnt[T_], sbase[T_];
    int tid = threadIdx.x;
    if (tid < T_) scnt[tid] = 0;
    __syncthreads();
    int i = blockIdx.x * 256 + tid;
    int t = (int)x[(long long)i * ROW];
    int r = atomicAdd(&scnt[t], 1);
    __syncthreads();
    if (tid < T_) sbase[tid] = atomicAdd(&g_counts[tid], scnt[tid]);
    __syncthreads();
    g_bucket[t * NATOM + sbase[t] + r] = i;
}

// ===========================================================================
// K2: layer-1 via mma.sync tf32; 256 atoms/CTA. Warp w owns m-tiles
//     wb=w (rows 16w..16w+16) and wb=w+8 (rows 128+16w..), and stages
//     those 32 rows itself -> zero block barriers in the mainloop.
// A frag map (m16n8k8): a0=(r=l>>2,k=l&3) a1=(r+8,k) a2=(r,k+4) a3=(r+8,k+4)
// ===========================================================================
__global__ void __launch_bounds__(256, 2)
k_mlp(const float* __restrict__ x,  const float* __restrict__ mask,
      const float* __restrict__ W1, const float* __restrict__ b1,
      const float* __restrict__ W2, const float* __restrict__ b2,
      const float* __restrict__ W3, const float* __restrict__ b3) {
    extern __shared__ float sm[];
    int* s_idx = (int*)&sm[S_IDX];
    const int tid  = threadIdx.x;
    const int warp = tid >> 5;
    const int lane = tid & 31;

    // ---- map block -> (type, tile) ----
    int t = -1, tile = 0, cnt = 0;
    {
        int rem = blockIdx.x;
        #pragma unroll
        for (int tt = 0; tt < T_; tt++) {
            int c  = g_counts[tt];
            int nt = (c + BM - 1) >> 8;
            if (t < 0) {
                if (rem < nt) { t = tt; tile = rem; cnt = c; }
                else rem -= nt;
            }
        }
    }
    if (t < 0) return;

    const uint32_t smb = smem_u32(sm);

    // ---- prologue: params + atom indices ----
    for (int i = tid; i < H1_ * H2_; i += 256)
        sm[S_W2 + i] = W2[t * H1_ * H2_ + i];
    if (tid < H1_) sm[S_B1 + tid] = b1[t * H1_ + tid];
    if (tid < H2_) sm[S_B2 + tid] = b2[t * H2_ + tid];
    if (tid < H2_) sm[S_W3 + tid] = W3[t * H2_ + tid];
    if (tid == 0) { sm[S_MISC] = g_corr[t]; sm[S_MISC + 1] = b3[t]; }
    {
        int gi = tile * BM + tid;
        s_idx[tid] = (gi < cnt) ? g_bucket[t * NATOM + gi] : -1;
    }
    __syncthreads();   // barrier 1: s_idx visible

    // warp-private staging base (floats)
    const int awbase = warp * AW_F;

    // this warp's 32 global atom slots: a<16 -> 16w+a ; a>=16 -> 128+16w+(a-16)
    // cached per-thread: lane a's slot for shuffle-free? simpler: read s_idx.

    // ---- stage one 32-k chunk of this warp's 32 rows ----
    auto issue_chunk = [&](int c, int buf) {
        const int k     = c * 32 + lane;
        const bool k_ok = (k < F_);
        uint32_t dst = smb + (uint32_t)((awbase + buf * ABUF_F + lane) * 4);
        #pragma unroll 8
        for (int a = 0; a < 32; a++) {
            int slot = (a < 16) ? (warp * 16 + a) : (112 + warp * 16 + a);
            int sid  = s_idx[slot];
            if (sid >= 0 && k_ok)
                cp_async4(dst, x + (long long)sid * ROW + 1 + k);
            else
                sts_zero(dst);
            dst += AROW * 4;
        }
    };

    // ---- accumulators ----
    float acc[2][8][4];
    #pragma unroll
    for (int m = 0; m < 2; m++)
        #pragma unroll
        for (int nt = 0; nt < 8; nt++)
            #pragma unroll
            for (int j = 0; j < 4; j++) acc[m][nt][j] = 0.0f;

    const float4* __restrict__ bfr = g_bfrag + t * (NKS * 8 * 32);

    // ---- one chunk of MMAs: 4 ks x 2 m x 8 nt x 3 ----
    // local row of m-tile m: m*16 + (l>>2); bank = 4*(l>>2)+(l&3)+8ksl: distinct
    auto compute_chunk = [&](int c, int buf) {
        const int rbase = awbase + buf * ABUF_F + (lane >> 2) * AROW + (lane & 3);
        #pragma unroll
        for (int ksl = 0; ksl < 4; ksl++) {
            const int ks = c * 4 + ksl;
            uint32_t Ahi[2][4], Alo[2][4];
            #pragma unroll
            for (int m = 0; m < 2; m++) {
                const int b0 = rbase + m * (16 * AROW) + ksl * 8;
                float a0 = sm[b0];
                float a1 = sm[b0 + 8 * AROW];
                float a2 = sm[b0 + 4];
                float a3 = sm[b0 + 8 * AROW + 4];
                float h;
                h = tf32_hi(a0); Ahi[m][0] = __float_as_uint(h);
                Alo[m][0] = __float_as_uint(a0 - h);
                h = tf32_hi(a1); Ahi[m][1] = __float_as_uint(h);
                Alo[m][1] = __float_as_uint(a1 - h);
                h = tf32_hi(a2); Ahi[m][2] = __float_as_uint(h);
                Alo[m][2] = __float_as_uint(a2 - h);
                h = tf32_hi(a3); Ahi[m][3] = __float_as_uint(h);
                Alo[m][3] = __float_as_uint(a3 - h);
            }
            #pragma unroll
            for (int nt = 0; nt < 8; nt++) {
                float4 bv = __ldg(&bfr[(ks * 8 + nt) * 32 + lane]);
                uint32_t bh0 = __float_as_uint(bv.x), bh1 = __float_as_uint(bv.y);
                uint32_t bl0 = __float_as_uint(bv.z), bl1 = __float_as_uint(bv.w);
                #pragma unroll
                for (int m = 0; m < 2; m++) {
                    mma_tf32(acc[m][nt], Ahi[m], bh0, bh1);   // Ah*Bh
                    mma_tf32(acc[m][nt], Ahi[m], bl0, bl1);   // Ah*Bl
                    mma_tf32(acc[m][nt], Alo[m], bh0, bh1);   // Al*Bh
                }
            }
        }
    };

    // ---- warp-autonomous double-buffered pipeline (no block barriers) ----
    issue_chunk(0, 0); CP_COMMIT();
    issue_chunk(1, 1); CP_COMMIT();
    CP_WAIT(1); __syncwarp();             // chunk0 resident (this warp)
    compute_chunk(0, 0);
    __syncwarp();                          // buf0 reads done (within warp)
    issue_chunk(2, 0); CP_COMMIT();
    CP_WAIT(1); __syncwarp();             // chunk1 resident
    compute_chunk(1, 1);
    __syncwarp();                          // buf1 reads done
    issue_chunk(3, 1); CP_COMMIT();
    CP_WAIT(1); __syncwarp();             // chunk2 resident
    compute_chunk(2, 0);
    CP_WAIT(0); __syncwarp();             // chunk3 resident
    compute_chunk(3, 1);
    __syncthreads();   // barrier 2: all staging reads done (h1s overlay)

    // ---- layer-1 epilogue: bias + relu -> h1s[atom][68] ----
    // D frag: c0=(r=l>>2, col=2*(l&3)) c1=(r,col+1) c2=(r+8,col) c3=(r+8,col+1)
    {
        #pragma unroll
        for (int m = 0; m < 2; m++) {
            const int r = (warp + m * 8) * 16 + (lane >> 2);
            #pragma unroll
            for (int nt = 0; nt < 8; nt++) {
                int cb = nt * 8 + 2 * (lane & 3);
                float ba = sm[S_B1 + cb], bb = sm[S_B1 + cb + 1];
                float2 v0 = make_float2(fmaxf(acc[m][nt][0] + ba, 0.0f),
                                        fmaxf(acc[m][nt][1] + bb, 0.0f));
                float2 v1 = make_float2(fmaxf(acc[m][nt][2] + ba, 0.0f),
                                        fmaxf(acc[m][nt][3] + bb, 0.0f));
                *(float2*)&sm[U_H1S + r * 68 + cb]       = v0;
                *(float2*)&sm[U_H1S + (r + 8) * 68 + cb] = v1;
            }
        }
    }
    __syncthreads();   // barrier 3: h1s complete

    // ---- layers 2+3 fused: all 256 threads, one atom slot each ----
    {
        float h1r[H1_];
        #pragma unroll
        for (int q = 0; q < 16; q++)
            *(float4*)&h1r[q * 4] = *(const float4*)&sm[U_H1S + tid * 68 + q * 4];

        unsigned long long accg[8];
        #pragma unroll
        for (int gp = 0; gp < 8; gp++)
            accg[gp] = *(const unsigned long long*)&sm[S_B2 + gp * 2];

        const ulonglong2* w2v = (const ulonglong2*)&sm[S_W2];
        #pragma unroll 8
        for (int k = 0; k < H1_; k++) {
            unsigned long long hkk = pack2(h1r[k], h1r[k]);
            #pragma unroll
            for (int gq = 0; gq < 4; gq++) {
                ulonglong2 w = w2v[k * 4 + gq];
                ffma2(accg[gq * 2],     hkk, w.x);
                ffma2(accg[gq * 2 + 1], hkk, w.y);
            }
        }

        float o = sm[S_MISC + 1];
        #pragma unroll
        for (int gp = 0; gp < 8; gp++) {
            float lo, hi; unpack2(accg[gp], lo, hi);
            o += fmaxf(lo, 0.0f) * sm[S_W3 + gp * 2]
               + fmaxf(hi, 0.0f) * sm[S_W3 + gp * 2 + 1];
        }
        int idx = s_idx[tid];
        if (idx >= 0)
            g_atom[idx] = (o + sm[S_MISC]) * mask[idx];
    }
}

// ===========================================================================
// K3: deterministic reduction — warp per molecule, fixed shuffle tree.
// ===========================================================================
__global__ void k_reduce(float* __restrict__ out) {
    int warp = threadIdx.x >> 5, lane = threadIdx.x & 31;
    int m = blockIdx.x * 8 + warp;
    const float* p = g_atom + m * A_;
    float s = p[lane] + p[lane + 32];
    #pragma unroll
    for (int o = 16; o > 0; o >>= 1) s += __shfl_xor_sync(0xffffffffu, s, o);
    if (lane == 0) out[m] = s;
}

// ===========================================================================
extern "C" void kernel_launch(void* const* d_in, const int* in_sizes, int n_in,
                              void* d_out, int out_size) {
    const float* x    = (const float*)d_in[0];
    const float* mask = (const float*)d_in[1];
    const float* W1   = (const float*)d_in[2];
    const float* b1   = (const float*)d_in[3];
    const float* W2   = (const float*)d_in[4];
    const float* b2   = (const float*)d_in[5];
    const float* W3   = (const float*)d_in[6];
    const float* b3   = (const float*)d_in[7];

    cudaFuncSetAttribute(k_mlp, cudaFuncAttributeMaxDynamicSharedMemorySize,
                         SMEM_BYTES);

    k_init<<<1, 32>>>(b1, W2, b2, W3, b3);
    k_binit<<<T_ * 8, 512>>>(W1);
    k_bucket<<<NATOM / 256, 256>>>(x);
    k_mlp<<<MLP_BLOCKS, 256, SMEM_BYTES>>>(x, mask, W1, b1, W2, b2, W3, b3);
    k_reduce<<<B_ / 8, 256>>>((float*)d_out);
}

// round 15
// speedup vs baseline: 1.1593x; 1.1593x over previous
#include <cuda_runtime.h>
#include <cstdint>

// ---------------------------------------------------------------------------
// MultiMolNet: per-atom typed 3-layer MLP + masked per-molecule sum.
// Identity: sum over all 8 type-MLPs = f_{type}(feats) + (C - Z_type),
// Z_t = f_t(0), C = sum_t Z_t  ->  one MLP eval per atom.
//
// R15: layer-1 on mma.sync.m16n8k16 BF16 (3-term hi/mid split; K=16 per
//      MMA halves both MMA count and B-fragment traffic vs tf32 k8 —
//      R12-R13 ncu plateaued ~116us with NO saturated pipe => cut work).
//      Warp-autonomous cp.async staging (zero mainloop block barriers),
//      BM=256, 2 m-tiles/warp, B fragments precomputed per type in gmem.
// ---------------------------------------------------------------------------

namespace {
constexpr int B_  = 4096;
constexpr int A_  = 64;
constexpr int F_  = 124;
constexpr int T_  = 8;
constexpr int H1_ = 64;
constexpr int H2_ = 16;
constexpr int NATOM = B_ * A_;     // 262144
constexpr int ROW   = F_ + 1;      // 125
constexpr int BM    = 256;         // atoms per CTA (two 128-row MMA tiles)
constexpr int MLP_BLOCKS = NATOM / BM + T_;   // 1032
constexpr int NCH   = 8;           // k chunks of 16 (one m16n8k16 step each)

// --- smem layout (float indices) ---
// Warp-private A staging: [8 warps][2 bufs][32 rows][24 floats]
//   (16 k + 8 pad; stride 24 -> fragment float2 reads are conflict-free:
//    banks 24r + 2c mod 32 all distinct per half-warp).
constexpr int AROW   = 24;
constexpr int ABUF_F = 32 * AROW;            // 768 floats per buffer
constexpr int AW_F   = 2 * ABUF_F;           // 1536 per warp
// h1s[256][68] overlays [0..17408) after layer-1 (barrier-protected).
constexpr int U_H1S = 0;
constexpr int S_W2   = 17408;       // 1024 (byte 69632, 16B aligned)
constexpr int S_B1   = S_W2 + 1024;
constexpr int S_B2   = S_B1 + 64;
constexpr int S_W3   = S_B2 + 16;
constexpr int S_MISC = S_W3 + 16;   // [0]=corr, [1]=b3
constexpr int S_IDX  = S_MISC + 4;  // 256 ints
constexpr int SMEM_FLOATS = S_IDX + BM;
constexpr int SMEM_BYTES  = SMEM_FLOATS * 4;   // ~75 KB -> 2 CTAs/SM
static_assert(8 * AW_F <= U_H1S + 17408, "staging fits under overlay");
}

// ---- scratch ----
__device__ int    g_counts[T_];
__device__ int    g_bucket[T_ * NATOM];
__device__ float  g_corr[T_];
__device__ float  g_atom[NATOM];
// B fragments per type: [8ks][8nt][32lane] x {Bx0,Bx1,By0,By1} (bf16x2 each)
__device__ uint4  g_bfrag[T_ * NCH * 8 * 32];   // 256 KB

// ---- helpers ----
__device__ __forceinline__ uint32_t smem_u32(const void* p) {
    return (uint32_t)__cvta_generic_to_shared(p);
}
// pack two f32 -> bf16x2 (lo = first arg, hi = second arg)
__device__ __forceinline__ uint32_t bf16x2_rn(float lo, float hi) {
    uint32_t r;
    asm("cvt.rn.bf16x2.f32 %0, %1, %2;" : "=r"(r) : "f"(hi), "f"(lo));
    return r;
}
__device__ __forceinline__ void cp_async4(uint32_t dst, const void* src) {
    asm volatile("cp.async.ca.shared.global [%0], [%1], 4;"
                 :: "r"(dst), "l"(src) : "memory");
}
__device__ __forceinline__ void sts_zero(uint32_t dst) {
    asm volatile("st.shared.b32 [%0], %1;" :: "r"(dst), "r"(0u));
}
#define CP_COMMIT() asm volatile("cp.async.commit_group;" ::: "memory")
#define CP_WAIT(n)  asm volatile("cp.async.wait_group %0;" :: "n"(n) : "memory")

// m16n8k16 bf16 MMA: D(f32) += A(bf16) * B(bf16). Row-major A, col-major B.
__device__ __forceinline__ void mma_bf16(float d[4], const uint32_t a[4],
                                         uint32_t b0, uint32_t b1) {
    asm volatile(
        "mma.sync.aligned.m16n8k16.row.col.f32.bf16.bf16.f32 "
        "{%0,%1,%2,%3}, {%4,%5,%6,%7}, {%8,%9}, {%0,%1,%2,%3};"
        : "+f"(d[0]), "+f"(d[1]), "+f"(d[2]), "+f"(d[3])
        : "r"(a[0]), "r"(a[1]), "r"(a[2]), "r"(a[3]), "r"(b0), "r"(b1));
}

// bf16 split of a float pair: X = rn_bf16x2(v0,v1); Y = rn_bf16x2(residuals)
__device__ __forceinline__ void bf16_split2(float v0, float v1,
                                            uint32_t& xo, uint32_t& yo) {
    uint32_t xp = bf16x2_rn(v0, v1);
    float f0 = __uint_as_float(xp << 16);
    float f1 = __uint_as_float(xp & 0xFFFF0000u);
    yo = bf16x2_rn(v0 - f0, v1 - f1);
    xo = xp;
}

// ---- f32x2 packed FMA (layer 2) ----
__device__ __forceinline__ void ffma2(unsigned long long& d,
                                      unsigned long long a, unsigned long long b) {
    asm("fma.rn.f32x2 %0, %1, %2, %3;" : "=l"(d) : "l"(a), "l"(b), "l"(d));
}
__device__ __forceinline__ unsigned long long pack2(float lo, float hi) {
    unsigned long long r;
    asm("mov.b64 %0, {%1, %2};" : "=l"(r) : "f"(lo), "f"(hi));
    return r;
}
__device__ __forceinline__ void unpack2(unsigned long long v, float& lo, float& hi) {
    asm("mov.b64 {%0, %1}, %2;" : "=f"(lo), "=f"(hi) : "l"(v));
}

// ===========================================================================
// K0: Z_t = f_t(0), corr_t = C - Z_t; zero counters.
// ===========================================================================
__global__ void k_init(const float* __restrict__ b1, const float* __restrict__ W2,
                       const float* __restrict__ b2, const float* __restrict__ W3,
                       const float* __restrict__ b3) {
    __shared__ float zs[T_];
    int t = threadIdx.x;
    if (t < T_) {
        g_counts[t] = 0;
        float h1z[H1_];
        #pragma unroll
        for (int h = 0; h < H1_; h++) h1z[h] = fmaxf(b1[t * H1_ + h], 0.0f);
        float o = b3[t];
        for (int g = 0; g < H2_; g++) {
            float s = b2[t * H2_ + g];
            #pragma unroll
            for (int k = 0; k < H1_; k++)
                s += h1z[k] * W2[t * H1_ * H2_ + k * H2_ + g];
            o += fmaxf(s, 0.0f) * W3[t * H2_ + g];
        }
        zs[t] = o;
    }
    __syncthreads();
    if (t < T_) {
        float C = 0.0f;
        #pragma unroll
        for (int tt = 0; tt < T_; tt++) C += zs[tt];
        g_corr[t] = C - zs[t];
    }
}

// ===========================================================================
// K0b: precompute B (W1) bf16 hi/mid fragments per type. 32 blocks x 512.
// m16n8k16 B frag (col-major): b0 = (k=2c..2c+1, n), b1 = (k+8..k+9, n),
//   n = l>>2, c = l&3.
// ===========================================================================
__global__ void k_binit(const float* __restrict__ W1) {
    int t    = blockIdx.x >> 2;
    int part = blockIdx.x & 3;
    const float* w = W1 + t * F_ * H1_;
    int s = part * 512 + threadIdx.x;             // 0..2047
    int l = s & 31, nt = (s >> 5) & 7, ks = s >> 8;
    int n  = nt * 8 + (l >> 2);
    int k0 = ks * 16 + 2 * (l & 3);
    float v00 = (k0     < F_) ? w[k0 * H1_ + n]       : 0.0f;
    float v01 = (k0 + 1 < F_) ? w[(k0 + 1) * H1_ + n] : 0.0f;
    float v10 = (k0 + 8 < F_) ? w[(k0 + 8) * H1_ + n] : 0.0f;
    float v11 = (k0 + 9 < F_) ? w[(k0 + 9) * H1_ + n] : 0.0f;
    uint32_t x0, y0, x1, y1;
    bf16_split2(v00, v01, x0, y0);
    bf16_split2(v10, v11, x1, y1);
    g_bfrag[t * (NCH * 8 * 32) + s] = make_uint4(x0, x1, y0, y1);
}

// ===========================================================================
// K1: bucket atom indices by type (order nondeterminism harmless).
// ===========================================================================
__global__ void k_bucket(const float* __restrict__ x) {
    __shared__ int scnt[T_], sbase[T_];
    int tid = threadIdx.x;
    if (tid < T_) scnt[tid] = 0;
    __syncthreads();
    int i = blockIdx.x * 256 + tid;
    int t = (int)x[(long long)i * ROW];
    int r = atomicAdd(&scnt[t], 1);
    __syncthreads();
    if (tid < T_) sbase[tid] = atomicAdd(&g_counts[tid], scnt[tid]);
    __syncthreads();
    g_bucket[t * NATOM + sbase[t] + r] = i;
}

// ===========================================================================
// K2: layer-1 via mma.sync bf16 k16; 256 atoms/CTA. Warp w owns m-tiles
//     wb=w (rows 16w..) and wb=w+8 (rows 128+16w..) and stages its own
//     32 rows (warp-autonomous double buffer, zero mainloop barriers).
// A frag (k16): a0=(r,2c..2c+1) a1=(r+8,..) a2=(r,2c+8..9) a3=(r+8,..)
// ===========================================================================
__global__ void __launch_bounds__(256, 2)
k_mlp(const float* __restrict__ x,  const float* __restrict__ mask,
      const float* __restrict__ W1, const float* __restrict__ b1,
      const float* __restrict__ W2, const float* __restrict__ b2,
      const float* __restrict__ W3, const float* __restrict__ b3) {
    extern __shared__ float sm[];
    int* s_idx = (int*)&sm[S_IDX];
    const int tid  = threadIdx.x;
    const int warp = tid >> 5;
    const int lane = tid & 31;

    // ---- map block -> (type, tile) ----
    int t = -1, tile = 0, cnt = 0;
    {
        int rem = blockIdx.x;
        #pragma unroll
        for (int tt = 0; tt < T_; tt++) {
            int c  = g_counts[tt];
            int nt = (c + BM - 1) >> 8;
            if (t < 0) {
                if (rem < nt) { t = tt; tile = rem; cnt = c; }
                else rem -= nt;
            }
        }
    }
    if (t < 0) return;

    const uint32_t smb = smem_u32(sm);

    // ---- prologue: params + atom indices ----
    for (int i = tid; i < H1_ * H2_; i += 256)
        sm[S_W2 + i] = W2[t * H1_ * H2_ + i];
    if (tid < H1_) sm[S_B1 + tid] = b1[t * H1_ + tid];
    if (tid < H2_) sm[S_B2 + tid] = b2[t * H2_ + tid];
    if (tid < H2_) sm[S_W3 + tid] = W3[t * H2_ + tid];
    if (tid == 0) { sm[S_MISC] = g_corr[t]; sm[S_MISC + 1] = b3[t]; }
    {
        int gi = tile * BM + tid;
        s_idx[tid] = (gi < cnt) ? g_bucket[t * NATOM + gi] : -1;
    }
    __syncthreads();   // barrier 1: s_idx visible

    const int awbase = warp * AW_F;

    // ---- stage one 16-k chunk of this warp's 32 rows ----
    // lane: kloc = l&15, row-half = l>>4; 16 iterations cover 32 rows.
    auto issue_chunk = [&](int c, int buf) {
        const int kloc = lane & 15;
        const int half = lane >> 4;
        const int k    = c * 16 + kloc;
        const bool k_ok = (k < F_);
        #pragma unroll 8
        for (int a = 0; a < 16; a++) {
            int i    = a * 2 + half;                 // local row 0..31
            int slot = (i < 16) ? (warp * 16 + i) : (112 + warp * 16 + i);
            int sid  = s_idx[slot];
            uint32_t dst = smb + (uint32_t)(
                (awbase + buf * ABUF_F + i * AROW + kloc) * 4);
            if (sid >= 0 && k_ok)
                cp_async4(dst, x + (long long)sid * ROW + 1 + k);
            else
                sts_zero(dst);
        }
    };

    // ---- accumulators ----
    float acc[2][8][4];
    #pragma unroll
    for (int m = 0; m < 2; m++)
        #pragma unroll
        for (int nt = 0; nt < 8; nt++)
            #pragma unroll
            for (int j = 0; j < 4; j++) acc[m][nt][j] = 0.0f;

    const uint4* __restrict__ bfr = g_bfrag + t * (NCH * 8 * 32);

    // ---- one chunk = one k16 MMA step: 2 m x 8 nt x 3 MMA ----
    auto compute_chunk = [&](int c, int buf) {
        const int base = awbase + buf * ABUF_F;
        const int roff = (lane >> 2) * AROW + 2 * (lane & 3);
        uint32_t Ax[2][4], Ay[2][4];
        #pragma unroll
        for (int m = 0; m < 2; m++) {
            const int rb = base + m * (16 * AROW) + roff;
            float2 p0 = *(const float2*)&sm[rb];
            float2 p1 = *(const float2*)&sm[rb + 8 * AROW];
            float2 p2 = *(const float2*)&sm[rb + 8];
            float2 p3 = *(const float2*)&sm[rb + 8 * AROW + 8];
            bf16_split2(p0.x, p0.y, Ax[m][0], Ay[m][0]);
            bf16_split2(p1.x, p1.y, Ax[m][1], Ay[m][1]);
            bf16_split2(p2.x, p2.y, Ax[m][2], Ay[m][2]);
            bf16_split2(p3.x, p3.y, Ax[m][3], Ay[m][3]);
        }
        #pragma unroll
        for (int nt = 0; nt < 8; nt++) {
            uint4 bv = __ldg(&bfr[(c * 8 + nt) * 32 + lane]);
            #pragma unroll
            for (int m = 0; m < 2; m++) {
                mma_bf16(acc[m][nt], Ax[m], bv.x, bv.y);   // Ax*Bx
                mma_bf16(acc[m][nt], Ax[m], bv.z, bv.w);   // Ax*By
                mma_bf16(acc[m][nt], Ay[m], bv.x, bv.y);   // Ay*Bx
            }
        }
    };

    // ---- warp-autonomous double-buffered pipeline over 8 chunks ----
    issue_chunk(0, 0); CP_COMMIT();
    issue_chunk(1, 1); CP_COMMIT();
    #pragma unroll
    for (int c = 0; c < NCH; c++) {
        if (c < NCH - 1) { CP_WAIT(1); } else { CP_WAIT(0); }
        __syncwarp();                      // chunk c resident (this warp)
        compute_chunk(c, c & 1);
        if (c < NCH - 2) {
            __syncwarp();                  // buf reads done (within warp)
            issue_chunk(c + 2, c & 1); CP_COMMIT();
        }
    }
    __syncthreads();   // barrier 2: all staging reads done (h1s overlay)

    // ---- layer-1 epilogue: bias + relu -> h1s[atom][68] ----
    // D frag: c0=(r=l>>2, col=2*(l&3)) c1=(r,col+1) c2=(r+8,col) c3=(r+8,col+1)
    {
        #pragma unroll
        for (int m = 0; m < 2; m++) {
            const int r = (warp + m * 8) * 16 + (lane >> 2);
            #pragma unroll
            for (int nt = 0; nt < 8; nt++) {
                int cb = nt * 8 + 2 * (lane & 3);
                float ba = sm[S_B1 + cb], bb = sm[S_B1 + cb + 1];
                float2 v0 = make_float2(fmaxf(acc[m][nt][0] + ba, 0.0f),
                                        fmaxf(acc[m][nt][1] + bb, 0.0f));
                float2 v1 = make_float2(fmaxf(acc[m][nt][2] + ba, 0.0f),
                                        fmaxf(acc[m][nt][3] + bb, 0.0f));
                *(float2*)&sm[U_H1S + r * 68 + cb]       = v0;
                *(float2*)&sm[U_H1S + (r + 8) * 68 + cb] = v1;
            }
        }
    }
    __syncthreads();   // barrier 3: h1s complete

    // ---- layers 2+3 fused: all 256 threads, one atom slot each ----
    {
        float h1r[H1_];
        #pragma unroll
        for (int q = 0; q < 16; q++)
            *(float4*)&h1r[q * 4] = *(const float4*)&sm[U_H1S + tid * 68 + q * 4];

        unsigned long long accg[8];
        #pragma unroll
        for (int gp = 0; gp < 8; gp++)
            accg[gp] = *(const unsigned long long*)&sm[S_B2 + gp * 2];

        const ulonglong2* w2v = (const ulonglong2*)&sm[S_W2];
        #pragma unroll 8
        for (int k = 0; k < H1_; k++) {
            unsigned long long hkk = pack2(h1r[k], h1r[k]);
            #pragma unroll
            for (int gq = 0; gq < 4; gq++) {
                ulonglong2 w = w2v[k * 4 + gq];
                ffma2(accg[gq * 2],     hkk, w.x);
                ffma2(accg[gq * 2 + 1], hkk, w.y);
            }
        }

        float o = sm[S_MISC + 1];
        #pragma unroll
        for (int gp = 0; gp < 8; gp++) {
            float lo, hi; unpack2(accg[gp], lo, hi);
            o += fmaxf(lo, 0.0f) * sm[S_W3 + gp * 2]
               + fmaxf(hi, 0.0f) * sm[S_W3 + gp * 2 + 1];
        }
        int idx = s_idx[tid];
        if (idx >= 0)
            g_atom[idx] = (o + sm[S_MISC]) * mask[idx];
    }
}

// ===========================================================================
// K3: deterministic reduction — warp per molecule, fixed shuffle tree.
// ===========================================================================
__global__ void k_reduce(float* __restrict__ out) {
    int warp = threadIdx.x >> 5, lane = threadIdx.x & 31;
    int m = blockIdx.x * 8 + warp;
    const float* p = g_atom + m * A_;
    float s = p[lane] + p[lane + 32];
    #pragma unroll
    for (int o = 16; o > 0; o >>= 1) s += __shfl_xor_sync(0xffffffffu, s, o);
    if (lane == 0) out[m] = s;
}

// ===========================================================================
extern "C" void kernel_launch(void* const* d_in, const int* in_sizes, int n_in,
                              void* d_out, int out_size) {
    const float* x    = (const float*)d_in[0];
    const float* mask = (const float*)d_in[1];
    const float* W1   = (const float*)d_in[2];
    const float* b1   = (const float*)d_in[3];
    const float* W2   = (const float*)d_in[4];
    const float* b2   = (const float*)d_in[5];
    const float* W3   = (const float*)d_in[6];
    const float* b3   = (const float*)d_in[7];

    cudaFuncSetAttribute(k_mlp, cudaFuncAttributeMaxDynamicSharedMemorySize,
                         SMEM_BYTES);

    k_init<<<1, 32>>>(b1, W2, b2, W3, b3);
    k_binit<<<T_ * 4, 512>>>(W1);
    k_bucket<<<NATOM / 256, 256>>>(x);
    k_mlp<<<MLP_BLOCKS, 256, SMEM_BYTES>>>(x, mask, W1, b1, W2, b2, W3, b3);
    k_reduce<<<B_ / 8, 256>>>((float*)d_out);
}